// round 16
// baseline (speedup 1.0000x reference)
#include <cuda_runtime.h>

#define N_EMB   512
#define EMB_D   64
#define HWSZ    4096
#define NTOK    131072
#define TPB     512
#define NCHUNK  (NTOK / 512)     // 256 chunks of 512 tokens
#define GRID_A  148
#define NREP    8

// Output packing (float32, reference tuple order)
#define OFF_RES 0ULL
#define OFF_ARG 8388608ULL
#define OFF_W   8519680ULL
#define OFF_CS  8552448ULL
#define OFF_EA  8552960ULL

#define SMEM_BYTES ((N_EMB * EMB_D + N_EMB) * 4)   // 133120 B

__device__ float g_histR[NREP][N_EMB];
__device__ float g_esumR[NREP][EMB_D * N_EMB];
__device__ float g_ww[N_EMB];
__device__ float g_wt[N_EMB * EMB_D];   // weight transposed: [j][d]
__device__ unsigned int g_work;
__device__ unsigned int g_done;

__device__ __forceinline__ unsigned long long ffma2(unsigned long long a,
                                                    unsigned long long b,
                                                    unsigned long long c) {
    unsigned long long d;
    asm("fma.rn.f32x2 %0, %1, %2, %3;" : "=l"(d) : "l"(a), "l"(b), "l"(c));
    return d;
}

__device__ __forceinline__ unsigned long long fadd2(unsigned long long a,
                                                    unsigned long long b) {
    unsigned long long d;
    asm("add.rn.f32x2 %0, %1, %2;" : "=l"(d) : "l"(a), "l"(b));
    return d;
}

__device__ __forceinline__ unsigned long long pack2(float lo, float hi) {
    unsigned long long r;
    asm("mov.b64 %0, {%1, %2};" : "=l"(r)
        : "r"(__float_as_uint(lo)), "r"(__float_as_uint(hi)));
    return r;
}

__device__ __forceinline__ void unpack2(unsigned long long v, float& lo, float& hi) {
    unsigned int a, b;
    asm("mov.b64 {%0, %1}, %2;" : "=r"(a), "=r"(b) : "l"(v));
    lo = __uint_as_float(a);
    hi = __uint_as_float(b);
}

// ---------------------------------------------------------------------------
// prep: zero replicated scratch, transpose weight, ||w||^2, reset counters
// ---------------------------------------------------------------------------
__global__ void prep_kernel(const float* __restrict__ w) {
    int idx = blockIdx.x * blockDim.x + threadIdx.x;
    if (idx == 0) { g_work = 0u; g_done = 0u; }
    if (idx < EMB_D * N_EMB) {
        #pragma unroll
        for (int r = 0; r < NREP; r++) g_esumR[r][idx] = 0.0f;
        int j = idx >> 6;
        int d = idx & 63;
        g_wt[idx] = w[d * N_EMB + j];
    }
    if (idx < N_EMB) {
        #pragma unroll
        for (int r = 0; r < NREP; r++) g_histR[r][idx] = 0.0f;
        float s = 0.0f;
        #pragma unroll
        for (int d = 0; d < EMB_D; d++) {
            float v = w[d * N_EMB + idx];
            s = __fadd_rn(s, __fmul_rn(v, v));
        }
        g_ww[idx] = s;
    }
}

// ---------------------------------------------------------------------------
// assign: 512 thr (4 warps/SMSP). Lane pairs split the d-dimension:
// even lane holds d[0:32), odd d[32:64) of the SAME 2 tokens (xp = 64 regs).
// Partial dots combined via shfl_xor(1). T=2 token-reuse kept (4:1 FMA:LDS).
// ---------------------------------------------------------------------------
extern __shared__ float smem_dyn[];

__global__ void __launch_bounds__(TPB, 1)
assign_kernel(const float* __restrict__ x,
              const float* __restrict__ cs_in,
              const float* __restrict__ ea_in,
              float* __restrict__ out) {
    float* w_s  = smem_dyn;                     // [512][64] j-major
    float* ww_s = smem_dyn + N_EMB * EMB_D;     // [512]
    __shared__ int s_chunk;
    __shared__ unsigned int s_rank;

    int tid  = threadIdx.x;
    int lane = tid & 31;
    int half = tid & 1;                 // 0: d[0:32), 1: d[32:64)
    int pair = (tid >> 1) & 255;        // token-pair id within chunk (0..255)
    int rep  = blockIdx.x & (NREP - 1);
    float* histR = g_histR[rep];
    float* esumR = g_esumR[rep];

    // Stage transposed weight once per CTA: coalesced, conflict-free
    {
        const float4* src = (const float4*)g_wt;
        float4* dst = (float4*)w_s;
        #pragma unroll
        for (int i = 0; i < (N_EMB * EMB_D / 4) / TPB; i++)
            dst[i * TPB + tid] = src[i * TPB + tid];
        ww_s[tid] = g_ww[tid];
    }

    for (;;) {
        __syncthreads();
        if (tid == 0) s_chunk = (int)atomicAdd(&g_work, 1u);
        __syncthreads();
        int c = s_chunk;
        if (c >= NCHUNK) break;

        // chunk = 512 consecutive tokens, never crosses a batch
        int tA = c * 512 + pair;           // token A; token B = tA + 256
        int b0 = tA >> 12;
        int hw0 = tA & (HWSZ - 1);
        const float* xa_p = x + (size_t)b0 * EMB_D * HWSZ + hw0;

        // This lane's d-half of both tokens: 16 dpairs each (64 regs total)
        unsigned long long xpa[16];
        unsigned long long xpb[16];
        int dbase = half * 16;             // first dpair of this half
        #pragma unroll
        for (int i = 0; i < 16; i++) {
            int dp = dbase + i;
            xpa[i] = pack2(xa_p[(2 * dp) * HWSZ],       xa_p[(2 * dp + 1) * HWSZ]);
            xpb[i] = pack2(xa_p[(2 * dp) * HWSZ + 256], xa_p[(2 * dp + 1) * HWSZ + 256]);
        }

        float bestA = 3.4e38f, bestB = 3.4e38f;
        int   biA = 0, biB = 0;

        #pragma unroll 1
        for (int j0 = 0; j0 < N_EMB; j0 += 2) {
            // this lane reads only its 128-byte half of each 256B row
            const ulonglong2* r0 =
                (const ulonglong2*)(w_s + (j0 + 0) * EMB_D) + half * 8;
            const ulonglong2* r1 =
                (const ulonglong2*)(w_s + (j0 + 1) * EMB_D) + half * 8;

            unsigned long long a0Ae = 0ULL, a0Ao = 0ULL, a0Be = 0ULL, a0Bo = 0ULL;
            unsigned long long a1Ae = 0ULL, a1Ao = 0ULL, a1Be = 0ULL, a1Bo = 0ULL;

            #pragma unroll
            for (int q = 0; q < 8; q++) {
                ulonglong2 v0 = r0[q];     // 2-address broadcast LDS.128
                ulonglong2 v1 = r1[q];
                unsigned long long xaE = xpa[2 * q], xaO = xpa[2 * q + 1];
                unsigned long long xbE = xpb[2 * q], xbO = xpb[2 * q + 1];
                a0Ae = ffma2(xaE, v0.x, a0Ae);  a0Ao = ffma2(xaO, v0.y, a0Ao);
                a0Be = ffma2(xbE, v0.x, a0Be);  a0Bo = ffma2(xbO, v0.y, a0Bo);
                a1Ae = ffma2(xaE, v1.x, a1Ae);  a1Ao = ffma2(xaO, v1.y, a1Ao);
                a1Be = ffma2(xbE, v1.x, a1Be);  a1Bo = ffma2(xbO, v1.y, a1Bo);
            }

            float lo, hi;
            float w0 = ww_s[j0], w1 = ww_s[j0 + 1];

            unpack2(fadd2(a0Ae, a0Ao), lo, hi);
            float p0A = __fadd_rn(lo, hi);
            unpack2(fadd2(a1Ae, a1Ao), lo, hi);
            float p1A = __fadd_rn(lo, hi);
            unpack2(fadd2(a0Be, a0Bo), lo, hi);
            float p0B = __fadd_rn(lo, hi);
            unpack2(fadd2(a1Be, a1Bo), lo, hi);
            float p1B = __fadd_rn(lo, hi);

            // combine halves with partner lane (fp add is commutative =>
            // both lanes get bit-identical sums)
            float dot0A = __fadd_rn(p0A, __shfl_xor_sync(0xFFFFFFFFu, p0A, 1));
            float dot1A = __fadd_rn(p1A, __shfl_xor_sync(0xFFFFFFFFu, p1A, 1));
            float dot0B = __fadd_rn(p0B, __shfl_xor_sync(0xFFFFFFFFu, p0B, 1));
            float dot1B = __fadd_rn(p1B, __shfl_xor_sync(0xFFFFFFFFu, p1B, 1));

            float d0A = __fmaf_rn(-2.0f, dot0A, w0);
            float d1A = __fmaf_rn(-2.0f, dot1A, w1);
            float d0B = __fmaf_rn(-2.0f, dot0B, w0);
            float d1B = __fmaf_rn(-2.0f, dot1B, w1);

            // strict < ascending j => first-min tie-break (jnp.argmin)
            if (d0A < bestA) { bestA = d0A; biA = j0;     }
            if (d1A < bestA) { bestA = d1A; biA = j0 + 1; }
            if (d0B < bestB) { bestB = d0B; biB = j0;     }
            if (d1B < bestB) { bestB = d1B; biB = j0 + 1; }
        }

        // ---- outputs: even lane owns token A, odd lane token B ----
        if (half == 0) {
            out[OFF_ARG + (size_t)tA] = (float)biA;
            float* ro = out + (size_t)b0 * EMB_D * HWSZ + hw0;
            const float4* wrow = (const float4*)(w_s + biA * EMB_D);
            #pragma unroll
            for (int i = 0; i < EMB_D / 4; i++) {
                float4 v = wrow[i];
                ro[(4 * i + 0) * HWSZ] = v.x;
                ro[(4 * i + 1) * HWSZ] = v.y;
                ro[(4 * i + 2) * HWSZ] = v.z;
                ro[(4 * i + 3) * HWSZ] = v.w;
            }
        } else {
            out[OFF_ARG + (size_t)tA + 256] = (float)biB;
            float* ro = out + (size_t)b0 * EMB_D * HWSZ + hw0 + 256;
            const float4* wrow = (const float4*)(w_s + biB * EMB_D);
            #pragma unroll
            for (int i = 0; i < EMB_D / 4; i++) {
                float4 v = wrow[i];
                ro[(4 * i + 0) * HWSZ] = v.x;
                ro[(4 * i + 1) * HWSZ] = v.y;
                ro[(4 * i + 2) * HWSZ] = v.z;
                ro[(4 * i + 3) * HWSZ] = v.w;
            }
        }

        // hist: warp-aggregated, parity-masked so each pair counts once
        {
            unsigned int mA = __match_any_sync(0xFFFFFFFFu, biA) & 0x55555555u;
            if (mA && (int)(__ffs(mA) - 1) == lane)
                atomicAdd(&histR[biA], (float)__popc(mA));
            unsigned int mB = __match_any_sync(0xFFFFFFFFu, biB) & 0xAAAAAAAAu;
            if (mB && (int)(__ffs(mB) - 1) == lane)
                atomicAdd(&histR[biB], (float)__popc(mB));
        }

        // esum: each lane adds its d-half for both tokens
        #pragma unroll
        for (int i = 0; i < 16; i++) {
            int dp = dbase + i;
            float lo, hi;
            unpack2(xpa[i], lo, hi);
            atomicAdd(&esumR[(2 * dp)     * N_EMB + biA], lo);
            atomicAdd(&esumR[(2 * dp + 1) * N_EMB + biA], hi);
            unpack2(xpb[i], lo, hi);
            atomicAdd(&esumR[(2 * dp)     * N_EMB + biB], lo);
            atomicAdd(&esumR[(2 * dp + 1) * N_EMB + biB], hi);
        }
    }

    // ------- merged finalize: last CTA does the EMA update -------
    __threadfence();
    __syncthreads();
    if (tid == 0) s_rank = atomicAdd(&g_done, 1u);
    __syncthreads();
    if (s_rank == GRID_A - 1) {
        float* red = smem_dyn;
        int j = tid;                      // TPB == N_EMB == 512

        const float DEC  = 0.99f;
        const float OMD  = (float)(1.0 - 0.99);
        const float EPSF = (float)1e-5;
        const float NEPS = (float)(N_EMB * 1e-5);

        float nidx = 0.0f;
        #pragma unroll
        for (int r = 0; r < NREP; r++) nidx += g_histR[r][j];
        if (nidx == 0.0f) nidx = 1.0f;
        float ncs = __fadd_rn(__fmul_rn(DEC, cs_in[j]), __fmul_rn(OMD, nidx));

        __syncthreads();
        red[j] = ncs;
        __syncthreads();
        #pragma unroll
        for (int s = N_EMB / 2; s > 0; s >>= 1) {
            if (j < s) red[j] += red[j + s];
            __syncthreads();
        }
        float n = red[0];

        float csn = __fmul_rn(__fdiv_rn(__fadd_rn(ncs, EPSF),
                                        __fadd_rn(n, NEPS)), n);

        out[OFF_CS + j] = ncs;

        for (int d = 0; d < EMB_D; d++) {
            int idx = d * N_EMB + j;
            float s0 = 0.0f;
            #pragma unroll
            for (int r = 0; r < NREP; r++) s0 += g_esumR[r][idx];
            float e = __fadd_rn(__fmul_rn(DEC, ea_in[idx]),
                                __fmul_rn(OMD, s0));
            out[OFF_EA + idx] = e;
            out[OFF_W  + idx] = __fdiv_rn(e, csn);
        }
    }
}

// ---------------------------------------------------------------------------
extern "C" void kernel_launch(void* const* d_in, const int* in_sizes, int n_in,
                              void* d_out, int out_size) {
    const float* x  = (const float*)d_in[0];
    const float* w  = (const float*)d_in[1];
    const float* cs = (const float*)d_in[2];
    const float* ea = (const float*)d_in[3];
    float* out = (float*)d_out;

    cudaFuncSetAttribute(assign_kernel,
                         cudaFuncAttributeMaxDynamicSharedMemorySize, SMEM_BYTES);

    prep_kernel<<<128, 256>>>(w);
    assign_kernel<<<GRID_A, TPB, SMEM_BYTES>>>(x, cs, ea, out);
}

// round 17
// speedup vs baseline: 1.1590x; 1.1590x over previous
#include <cuda_runtime.h>

#define N_EMB   512
#define EMB_D   64
#define HWSZ    4096
#define NTOK    131072
#define TPB     256
#define NCHUNK  (NTOK / 512)     // 256 chunks of 512 tokens
#define GRID_A  148
#define NREP    8

// Output packing (float32, reference tuple order)
#define OFF_RES 0ULL
#define OFF_ARG 8388608ULL
#define OFF_W   8519680ULL
#define OFF_CS  8552448ULL
#define OFF_EA  8552960ULL

#define SMEM_BYTES ((N_EMB * EMB_D + N_EMB) * 4)   // 133120 B

__device__ float g_histR[NREP][N_EMB];
__device__ float g_esumR[NREP][EMB_D * N_EMB];
__device__ float g_ww[N_EMB];
__device__ float g_wt[N_EMB * EMB_D];   // weight transposed: [j][d]
__device__ unsigned int g_work;
__device__ unsigned int g_done;

__device__ __forceinline__ unsigned long long ffma2(unsigned long long a,
                                                    unsigned long long b,
                                                    unsigned long long c) {
    unsigned long long d;
    asm("fma.rn.f32x2 %0, %1, %2, %3;" : "=l"(d) : "l"(a), "l"(b), "l"(c));
    return d;
}

__device__ __forceinline__ unsigned long long fadd2(unsigned long long a,
                                                    unsigned long long b) {
    unsigned long long d;
    asm("add.rn.f32x2 %0, %1, %2;" : "=l"(d) : "l"(a), "l"(b));
    return d;
}

__device__ __forceinline__ unsigned long long pack2(float lo, float hi) {
    unsigned long long r;
    asm("mov.b64 %0, {%1, %2};" : "=l"(r)
        : "r"(__float_as_uint(lo)), "r"(__float_as_uint(hi)));
    return r;
}

__device__ __forceinline__ void unpack2(unsigned long long v, float& lo, float& hi) {
    unsigned int a, b;
    asm("mov.b64 {%0, %1}, %2;" : "=r"(a), "=r"(b) : "l"(v));
    lo = __uint_as_float(a);
    hi = __uint_as_float(b);
}

// ---------------------------------------------------------------------------
// prep: zero replicated scratch, transpose weight, ||w||^2, reset counters
// ---------------------------------------------------------------------------
__global__ void prep_kernel(const float* __restrict__ w) {
    int idx = blockIdx.x * blockDim.x + threadIdx.x;
    if (idx == 0) { g_work = 0u; g_done = 0u; }
    if (idx < EMB_D * N_EMB) {
        #pragma unroll
        for (int r = 0; r < NREP; r++) g_esumR[r][idx] = 0.0f;
        int j = idx >> 6;
        int d = idx & 63;
        g_wt[idx] = w[d * N_EMB + j];
    }
    if (idx < N_EMB) {
        #pragma unroll
        for (int r = 0; r < NREP; r++) g_histR[r][idx] = 0.0f;
        float s = 0.0f;
        #pragma unroll
        for (int d = 0; d < EMB_D; d++) {
            float v = w[d * N_EMB + idx];
            s = __fadd_rn(s, __fmul_rn(v, v));
        }
        g_ww[idx] = s;
    }
}

// ---------------------------------------------------------------------------
// assign: 256 thr (2 warps/SMSP). Lane PAIRS share 4 tokens, splitting the
// d-dimension: even lane d[0:32), odd d[32:64). 8:1 FMA:LDS ratio.
// Partial dots combined via shfl_xor(1) — bit-identical in both lanes.
// ---------------------------------------------------------------------------
extern __shared__ float smem_dyn[];

__global__ void __launch_bounds__(TPB, 1)
assign_kernel(const float* __restrict__ x,
              const float* __restrict__ cs_in,
              const float* __restrict__ ea_in,
              float* __restrict__ out) {
    float* w_s  = smem_dyn;                     // [512][64] j-major
    float* ww_s = smem_dyn + N_EMB * EMB_D;     // [512]
    __shared__ int s_chunk;
    __shared__ unsigned int s_rank;

    int tid  = threadIdx.x;
    int lane = tid & 31;
    int half = tid & 1;                 // 0: d[0:32), 1: d[32:64)
    int pairg = tid >> 1;               // pair id 0..127
    int rep  = blockIdx.x & (NREP - 1);
    float* histR = g_histR[rep];
    float* esumR = g_esumR[rep];

    // Stage transposed weight once per CTA: coalesced, conflict-free
    {
        const float4* src = (const float4*)g_wt;
        float4* dst = (float4*)w_s;
        #pragma unroll
        for (int i = 0; i < (N_EMB * EMB_D / 4) / TPB; i++)
            dst[i * TPB + tid] = src[i * TPB + tid];
        ww_s[tid]       = g_ww[tid];
        ww_s[tid + 256] = g_ww[tid + 256];
    }

    for (;;) {
        __syncthreads();
        if (tid == 0) s_chunk = (int)atomicAdd(&g_work, 1u);
        __syncthreads();
        int c = s_chunk;
        if (c >= NCHUNK) break;

        // chunk = 512 consecutive tokens; pair owns tokens {p, p+128, p+256, p+384}
        int base = c * 512;
        int b0   = base >> 12;
        int hw0  = (base & (HWSZ - 1)) + pairg;
        const float* xbp = x + (size_t)b0 * EMB_D * HWSZ + hw0;

        // This lane's d-half of 4 tokens: 16 dpairs x 4 = 64 u64 = 128 regs
        unsigned long long xp[4][16];
        int dbase = half * 16;
        #pragma unroll
        for (int i = 0; i < 16; i++) {
            int dp = dbase + i;
            const float* pe = xbp + (2 * dp) * HWSZ;
            const float* po = xbp + (2 * dp + 1) * HWSZ;
            #pragma unroll
            for (int t = 0; t < 4; t++)
                xp[t][i] = pack2(pe[t * 128], po[t * 128]);
        }

        float best[4] = {3.4e38f, 3.4e38f, 3.4e38f, 3.4e38f};
        int   bi[4]   = {0, 0, 0, 0};

        #pragma unroll 1
        for (int j0 = 0; j0 < N_EMB; j0 += 2) {
            // this lane reads only its 128-byte half of each 256B row
            const ulonglong2* r0 =
                (const ulonglong2*)(w_s + (j0 + 0) * EMB_D) + half * 8;
            const ulonglong2* r1 =
                (const ulonglong2*)(w_s + (j0 + 1) * EMB_D) + half * 8;

            unsigned long long acc[2][4][2];
            #pragma unroll
            for (int j = 0; j < 2; j++)
                #pragma unroll
                for (int t = 0; t < 4; t++) {
                    acc[j][t][0] = 0ULL;
                    acc[j][t][1] = 0ULL;
                }

            #pragma unroll
            for (int q = 0; q < 8; q++) {
                ulonglong2 v0 = r0[q];     // 2-address broadcast LDS.128
                ulonglong2 v1 = r1[q];
                #pragma unroll
                for (int t = 0; t < 4; t++) {
                    unsigned long long xe = xp[t][2 * q];
                    unsigned long long xo = xp[t][2 * q + 1];
                    acc[0][t][0] = ffma2(xe, v0.x, acc[0][t][0]);
                    acc[0][t][1] = ffma2(xo, v0.y, acc[0][t][1]);
                    acc[1][t][0] = ffma2(xe, v1.x, acc[1][t][0]);
                    acc[1][t][1] = ffma2(xo, v1.y, acc[1][t][1]);
                }
            }

            float w0 = ww_s[j0], w1 = ww_s[j0 + 1];
            #pragma unroll
            for (int t = 0; t < 4; t++) {
                float lo, hi;
                unpack2(fadd2(acc[0][t][0], acc[0][t][1]), lo, hi);
                float p0 = __fadd_rn(lo, hi);
                unpack2(fadd2(acc[1][t][0], acc[1][t][1]), lo, hi);
                float p1 = __fadd_rn(lo, hi);

                // combine halves with partner lane (commutative fp add =>
                // both lanes get bit-identical sums)
                float dot0 = __fadd_rn(p0, __shfl_xor_sync(0xFFFFFFFFu, p0, 1));
                float dot1 = __fadd_rn(p1, __shfl_xor_sync(0xFFFFFFFFu, p1, 1));

                float d0 = __fmaf_rn(-2.0f, dot0, w0);
                float d1 = __fmaf_rn(-2.0f, dot1, w1);

                // strict < ascending j => first-min tie-break (jnp.argmin)
                if (d0 < best[t]) { best[t] = d0; bi[t] = j0;     }
                if (d1 < best[t]) { best[t] = d1; bi[t] = j0 + 1; }
            }
        }

        // ---- outputs: even lane owns tokens 0,1; odd lane tokens 2,3 ----
        {
            int town = half * 2;
            #pragma unroll
            for (int tt = 0; tt < 2; tt++) {
                int t = town + tt;
                int tok = base + pairg + t * 128;
                out[OFF_ARG + (size_t)tok] = (float)bi[t];
                float* ro = out + (size_t)b0 * EMB_D * HWSZ + hw0 + t * 128;
                const float4* wrow = (const float4*)(w_s + bi[t] * EMB_D);
                #pragma unroll
                for (int i = 0; i < EMB_D / 4; i++) {
                    float4 v = wrow[i];
                    ro[(4 * i + 0) * HWSZ] = v.x;
                    ro[(4 * i + 1) * HWSZ] = v.y;
                    ro[(4 * i + 2) * HWSZ] = v.z;
                    ro[(4 * i + 3) * HWSZ] = v.w;
                }
            }
        }

        // hist: warp-aggregated, even-parity masked (each pair counts once)
        #pragma unroll
        for (int t = 0; t < 4; t++) {
            unsigned int m = __match_any_sync(0xFFFFFFFFu, bi[t]) & 0x55555555u;
            if (m && (int)(__ffs(m) - 1) == lane)
                atomicAdd(&histR[bi[t]], (float)__popc(m));
        }

        // esum: each lane adds its own d-half for all 4 tokens
        #pragma unroll
        for (int i = 0; i < 16; i++) {
            int dp = dbase + i;
            #pragma unroll
            for (int t = 0; t < 4; t++) {
                float lo, hi;
                unpack2(xp[t][i], lo, hi);
                atomicAdd(&esumR[(2 * dp)     * N_EMB + bi[t]], lo);
                atomicAdd(&esumR[(2 * dp + 1) * N_EMB + bi[t]], hi);
            }
        }
    }

    // ------- merged finalize: last CTA does the EMA update -------
    __threadfence();
    __syncthreads();
    if (tid == 0) s_rank = atomicAdd(&g_done, 1u);
    __syncthreads();
    if (s_rank == GRID_A - 1) {
        float* red = smem_dyn;

        const float DEC  = 0.99f;
        const float OMD  = (float)(1.0 - 0.99);
        const float EPSF = (float)1e-5;
        const float NEPS = (float)(N_EMB * 1e-5);

        float ncs0, ncs1;
        {
            float n0 = 0.0f, n1 = 0.0f;
            #pragma unroll
            for (int r = 0; r < NREP; r++) {
                n0 += g_histR[r][tid];
                n1 += g_histR[r][tid + 256];
            }
            if (n0 == 0.0f) n0 = 1.0f;
            if (n1 == 0.0f) n1 = 1.0f;
            ncs0 = __fadd_rn(__fmul_rn(DEC, cs_in[tid]), __fmul_rn(OMD, n0));
            ncs1 = __fadd_rn(__fmul_rn(DEC, cs_in[tid + 256]), __fmul_rn(OMD, n1));
        }

        __syncthreads();
        red[tid] = ncs0 + ncs1;
        __syncthreads();
        #pragma unroll
        for (int s = 128; s > 0; s >>= 1) {
            if (tid < s) red[tid] += red[tid + s];
            __syncthreads();
        }
        float n = red[0];

        float csn0 = __fmul_rn(__fdiv_rn(__fadd_rn(ncs0, EPSF),
                                         __fadd_rn(n, NEPS)), n);
        float csn1 = __fmul_rn(__fdiv_rn(__fadd_rn(ncs1, EPSF),
                                         __fadd_rn(n, NEPS)), n);

        out[OFF_CS + tid]       = ncs0;
        out[OFF_CS + tid + 256] = ncs1;

        for (int d = 0; d < EMB_D; d++) {
            int i0 = d * N_EMB + tid;
            int i1 = i0 + 256;
            float s0 = 0.0f, s1 = 0.0f;
            #pragma unroll
            for (int r = 0; r < NREP; r++) {
                s0 += g_esumR[r][i0];
                s1 += g_esumR[r][i1];
            }
            float e0 = __fadd_rn(__fmul_rn(DEC, ea_in[i0]), __fmul_rn(OMD, s0));
            float e1 = __fadd_rn(__fmul_rn(DEC, ea_in[i1]), __fmul_rn(OMD, s1));
            out[OFF_EA + i0] = e0;
            out[OFF_EA + i1] = e1;
            out[OFF_W  + i0] = __fdiv_rn(e0, csn0);
            out[OFF_W  + i1] = __fdiv_rn(e1, csn1);
        }
    }
}

// ---------------------------------------------------------------------------
extern "C" void kernel_launch(void* const* d_in, const int* in_sizes, int n_in,
                              void* d_out, int out_size) {
    const float* x  = (const float*)d_in[0];
    const float* w  = (const float*)d_in[1];
    const float* cs = (const float*)d_in[2];
    const float* ea = (const float*)d_in[3];
    float* out = (float*)d_out;

    cudaFuncSetAttribute(assign_kernel,
                         cudaFuncAttributeMaxDynamicSharedMemorySize, SMEM_BYTES);

    prep_kernel<<<128, 256>>>(w);
    assign_kernel<<<GRID_A, TPB, SMEM_BYTES>>>(x, cs, ea, out);
}